// round 7
// baseline (speedup 1.0000x reference)
#include <cuda_runtime.h>
#include <cuda_bf16.h>

#define HH 1024
#define WW 2048
#define HWSZ (HH * WW)
#define NC 19
#define RAD 16
#define INV_LOG19 0.3396224f   // 1 / ln(19)

// -------- scratch (device globals: allocation-free per harness rules) -------
__device__ unsigned char g_predict[HWSZ];   // argmax class per pixel
__device__ float         g_wpe[HWSZ];       // weighted pixel entropy / ln19
__device__ int           g_tile_ctr;        // persistent-kernel work queue

// ============================================================================
// Pass A: per-pixel softmax entropy + argmax + weighted entropy  (unchanged,
// measured 72% DRAM roofline)
// ============================================================================
__global__ __launch_bounds__(256) void passA(const float* __restrict__ logit,
                                             const float* __restrict__ cw) {
    int i = blockIdx.x * blockDim.x + threadIdx.x;
    if (i >= HWSZ) return;

    float v[NC];
#pragma unroll
    for (int c = 0; c < NC; c++) v[c] = logit[c * HWSZ + i];

    float m = v[0];
    int am = 0;
#pragma unroll
    for (int c = 1; c < NC; c++) {
        if (v[c] > m) { m = v[c]; am = c; }
    }

    float S = 0.f, T = 0.f;
#pragma unroll
    for (int c = 0; c < NC; c++) {
        float d = v[c] - m;
        float e = __expf(d);
        S += e;
        T += e * d;
    }
    float ent = __logf(S) - T * __frcp_rn(S);

    g_predict[i] = (unsigned char)am;
    g_wpe[i] = ent * cw[am] * INV_LOG19;
}

__global__ void zeroCtr() { g_tile_ctr = 0; }

// ============================================================================
// Fused passBC, persistent version. Tile: 256 out-cols x 8 out-rows,
// 1024 tiles total, dynamically stolen by 592 resident blocks (4/SM).
// 24B/pixel records split: uint4 A[] (classes 0..15) + uint2 B[] (16..18|fs).
// ============================================================================
#define W_OUT 256
#define W_IN  288                  // + 2*RAD halo columns
#define HB    8                    // output rows per block
#define CHC_F 8                    // outputs per horizontal-slider task
#define NTILES ((WW / W_OUT) * (HH / HB))   // 8 * 128 = 1024
#define STRIDE_A (W_IN * 4 + 4)    // 1156 words; %32==4 -> r*4 distinct banks
#define STRIDE_B (W_IN * 2 + 2)    // 578 words;  %32==2 -> 2r distinct banks
#define SMEM_WORDS (HB * (STRIDE_A + STRIDE_B))
#define SMEM_BYTES (SMEM_WORDS * 4)   // 55488 B
#define NBLOCKS 592                // 4 per SM x 148 SMs

__device__ __forceinline__ void pk_add(unsigned long long& w0,
                                       unsigned long long& w1,
                                       unsigned& w2, int cls) {
    if (cls < 8)       w0 += 1ull << (cls * 8);
    else if (cls < 16) w1 += 1ull << ((cls & 7) * 8);
    else               w2 += 1u << ((cls - 16) * 8);
}
__device__ __forceinline__ void pk_sub(unsigned long long& w0,
                                       unsigned long long& w1,
                                       unsigned& w2, int cls) {
    if (cls < 8)       w0 -= 1ull << (cls * 8);
    else if (cls < 16) w1 -= 1ull << ((cls & 7) * 8);
    else               w2 -= 1u << ((cls - 16) * 8);
}

// unpack 4 bytes into two u32 halfword pairs
#define PLO(w) __byte_perm((w), 0, 0x4140)
#define PHI(w) __byte_perm((w), 0, 0x4342)

__device__ __forceinline__ void srec_add(const unsigned* __restrict__ smA,
                                         const unsigned* __restrict__ smB,
                                         int s, unsigned* h, float& fs) {
    uint4 a = *(const uint4*)(smA + s * 4);
    uint2 b = *(const uint2*)(smB + s * 2);
    h[0] += PLO(a.x); h[1] += PHI(a.x);
    h[2] += PLO(a.y); h[3] += PHI(a.y);
    h[4] += PLO(a.z); h[5] += PHI(a.z);
    h[6] += PLO(a.w); h[7] += PHI(a.w);
    h[8] += PLO(b.x); h[9] += PHI(b.x);
    fs += __uint_as_float(b.y);
}
__device__ __forceinline__ void srec_sub(const unsigned* __restrict__ smA,
                                         const unsigned* __restrict__ smB,
                                         int s, unsigned* h, float& fs) {
    uint4 a = *(const uint4*)(smA + s * 4);
    uint2 b = *(const uint2*)(smB + s * 2);
    h[0] -= PLO(a.x); h[1] -= PHI(a.x);
    h[2] -= PLO(a.y); h[3] -= PHI(a.y);
    h[4] -= PLO(a.z); h[5] -= PHI(a.z);
    h[6] -= PLO(a.w); h[7] -= PHI(a.w);
    h[8] -= PLO(b.x); h[9] -= PHI(b.x);
    fs -= __uint_as_float(b.y);
}

__global__ __launch_bounds__(256, 4) void fusedBC(float* __restrict__ out) {
    extern __shared__ unsigned sm[];
    __shared__ int s_tile;
    unsigned* smA = sm;                          // HB * STRIDE_A words
    unsigned* smB = sm + HB * STRIDE_A;          // HB * STRIDE_B words
    const int tid = threadIdx.x;

    for (;;) {
        if (tid == 0) s_tile = atomicAdd(&g_tile_ctr, 1);
        __syncthreads();
        const int t = s_tile;
        if (t >= NTILES) return;                 // uniform exit, no divergence

        const int x0 = (t & 7) * W_OUT;
        const int y0 = (t >> 3) * HB;

        // ------------- Phase 1: vertical 33-tap sliders (288 cols) ----------
        for (int j = tid; j < W_IN; j += 256) {
            int xg = x0 - RAD + j;
            bool valid = (xg >= 0) && (xg < WW);

            unsigned long long w0 = 0, w1 = 0;
            unsigned w2 = 0;
            float fs = 0.f;
            if (valid) {
#pragma unroll
                for (int yi = 0; yi < 33; yi++) {
                    int y = y0 - RAD + yi;
                    if (y >= 0 && y < HH) {
                        int idx = y * WW + xg;
                        fs += g_wpe[idx];
                        pk_add(w0, w1, w2, g_predict[idx]);
                    }
                }
            }
#pragma unroll
            for (int r = 0; r < HB; r++) {
                *(uint4*)(smA + r * STRIDE_A + j * 4) =
                    make_uint4((unsigned)w0, (unsigned)(w0 >> 32),
                               (unsigned)w1, (unsigned)(w1 >> 32));
                *(uint2*)(smB + r * STRIDE_B + j * 2) =
                    make_uint2(w2, __float_as_uint(fs));
                if (valid) {
                    int ya = y0 + r + RAD + 1;
                    if (ya < HH) {
                        int ia = ya * WW + xg;
                        fs += g_wpe[ia];
                        pk_add(w0, w1, w2, g_predict[ia]);
                    }
                    int yr = y0 + r - RAD;
                    if (yr >= 0) {
                        int ir = yr * WW + xg;
                        fs -= g_wpe[ir];
                        pk_sub(w0, w1, w2, g_predict[ir]);
                    }
                }
            }
        }
        __syncthreads();

        // ------------- Phase 2: horizontal 33-tap sliders (256 tasks) -------
        {
            const int r = tid & 7;      // low bits -> conflict-free LDS phases
            const int c = tid >> 3;
            const int xo = x0 + c * CHC_F;
            const unsigned* rowA = smA + r * STRIDE_A;
            const unsigned* rowB = smB + r * STRIDE_B;

            int yy = y0 + r;
            int wy = min(yy + RAD, HH - 1) - max(yy - RAD, 0) + 1;

            unsigned h[10];
#pragma unroll
            for (int i = 0; i < 10; i++) h[i] = 0;
            float fs = 0.f;

#pragma unroll
            for (int si = 0; si < 33; si++)
                srec_add(rowA, rowB, c * CHC_F + si, h, fs);

#pragma unroll
            for (int k4 = 0; k4 < CHC_F / 4; k4++) {
                float s4[4], i4[4], u4[4];
#pragma unroll
                for (int kk = 0; kk < 4; kk++) {
                    int k = k4 * 4 + kk;
                    int x = xo + k;
                    int wx = min(x + RAD, WW - 1) - max(x - RAD, 0) + 1;
                    float fcount = (float)(wx * wy);   // exact window size
                    float invc = __frcp_rn(fcount);
                    float eps = 1e-6f * fcount;

                    float acc0 = 0.f, acc1 = 0.f;      // two chains for ILP
#pragma unroll
                    for (int p = 0; p < 10; p++) {
                        float slo = (float)(h[p] & 0xFFFFu);
                        float shi = (float)(h[p] >> 16);
                        acc0 += slo * __logf(slo + eps);
                        if (p != 9)                    // lane 19 is zero pad
                            acc1 += shi * __logf(shi + eps);
                    }
                    float impurity = (__logf(fcount) - (acc0 + acc1) * invc)
                                     * INV_LOG19;
                    float unc = fs * invc;

                    s4[kk] = impurity * unc;
                    i4[kk] = impurity;
                    u4[kk] = unc;

                    if (k < CHC_F - 1) {
                        srec_add(rowA, rowB, c * CHC_F + k + 33, h, fs);
                        srec_sub(rowA, rowB, c * CHC_F + k, h, fs);
                    }
                }
                int o = yy * WW + xo + k4 * 4;
                *(float4*)(out + o)            = make_float4(s4[0], s4[1], s4[2], s4[3]);
                *(float4*)(out + HWSZ + o)     = make_float4(i4[0], i4[1], i4[2], i4[3]);
                *(float4*)(out + 2 * HWSZ + o) = make_float4(u4[0], u4[1], u4[2], u4[3]);
            }
        }
        __syncthreads();   // all phase-2 reads done before next tile's writes
    }
}

// ============================================================================
extern "C" void kernel_launch(void* const* d_in, const int* in_sizes, int n_in,
                              void* d_out, int out_size) {
    const float* logit = (const float*)d_in[0];
    const float* cw    = (const float*)d_in[1];
    float* out = (float*)d_out;

    cudaFuncSetAttribute(fusedBC, cudaFuncAttributeMaxDynamicSharedMemorySize,
                         SMEM_BYTES);

    zeroCtr<<<1, 1>>>();
    passA<<<HWSZ / 256, 256>>>(logit, cw);
    fusedBC<<<NBLOCKS, 256, SMEM_BYTES>>>(out);
}

// round 8
// speedup vs baseline: 1.6245x; 1.6245x over previous
#include <cuda_runtime.h>
#include <cuda_bf16.h>
#include <cuda_fp16.h>

#define HH 1024
#define WW 2048
#define HWSZ (HH * WW)
#define NC 19
#define RAD 16
#define INV_LOG19 0.3396224f   // 1 / ln(19)

// -------- scratch (device globals: allocation-free per harness rules) -------
// packed per-pixel record: bits[16:21) = argmax class, bits[0:16) = fp16 wpe
__device__ unsigned g_packed[HWSZ];

// ============================================================================
// Pass A: per-pixel softmax entropy + argmax + weighted entropy -> packed 4B
// ============================================================================
__global__ __launch_bounds__(256) void passA(const float* __restrict__ logit,
                                             const float* __restrict__ cw) {
    int i = blockIdx.x * blockDim.x + threadIdx.x;
    if (i >= HWSZ) return;

    float v[NC];
#pragma unroll
    for (int c = 0; c < NC; c++) v[c] = logit[c * HWSZ + i];

    float m = v[0];
    int am = 0;
#pragma unroll
    for (int c = 1; c < NC; c++) {
        if (v[c] > m) { m = v[c]; am = c; }
    }

    float S = 0.f, T = 0.f;
#pragma unroll
    for (int c = 0; c < NC; c++) {
        float d = v[c] - m;
        float e = __expf(d);
        S += e;
        T += e * d;
    }
    float ent = __logf(S) - T * __frcp_rn(S);
    float wpe = ent * cw[am] * INV_LOG19;

    g_packed[i] = ((unsigned)am << 16)
                | (unsigned)__half_as_ushort(__float2half_rn(wpe));
}

// ============================================================================
// Fused passBC. Tile: 256 out-cols x 8 out-rows, grid (8,128)=1024 blocks.
// blockDim = 288 = W_IN: exactly one vertical slider per column (no straggler).
// 24B/pixel smem records: uint4 A[] (classes 0..15) + uint2 B[] (16..18|fs).
// ============================================================================
#define W_OUT 256
#define W_IN  288                  // + 2*RAD halo columns == blockDim
#define HB    8                    // output rows per block
#define CHC_F 8                    // outputs per horizontal-slider task
#define STRIDE_A (W_IN * 4 + 4)    // 1156 words; %32==4 -> r*4 distinct banks
#define STRIDE_B (W_IN * 2 + 2)    // 578 words;  %32==2 -> 2r distinct banks
#define SMEM_WORDS (HB * (STRIDE_A + STRIDE_B))
#define SMEM_BYTES (SMEM_WORDS * 4)   // 55488 B

__device__ __forceinline__ void pk_add(unsigned long long& w0,
                                       unsigned long long& w1,
                                       unsigned& w2, int cls) {
    if (cls < 8)       w0 += 1ull << (cls * 8);
    else if (cls < 16) w1 += 1ull << ((cls & 7) * 8);
    else               w2 += 1u << ((cls - 16) * 8);
}
__device__ __forceinline__ void pk_sub(unsigned long long& w0,
                                       unsigned long long& w1,
                                       unsigned& w2, int cls) {
    if (cls < 8)       w0 -= 1ull << (cls * 8);
    else if (cls < 16) w1 -= 1ull << ((cls & 7) * 8);
    else               w2 -= 1u << ((cls - 16) * 8);
}

// unpack 4 bytes into two u32 halfword pairs
#define PLO(w) __byte_perm((w), 0, 0x4140)
#define PHI(w) __byte_perm((w), 0, 0x4342)

__device__ __forceinline__ void srec_add(const unsigned* __restrict__ smA,
                                         const unsigned* __restrict__ smB,
                                         int s, unsigned* h, float& fs) {
    uint4 a = *(const uint4*)(smA + s * 4);
    uint2 b = *(const uint2*)(smB + s * 2);
    h[0] += PLO(a.x); h[1] += PHI(a.x);
    h[2] += PLO(a.y); h[3] += PHI(a.y);
    h[4] += PLO(a.z); h[5] += PHI(a.z);
    h[6] += PLO(a.w); h[7] += PHI(a.w);
    h[8] += PLO(b.x); h[9] += PHI(b.x);
    fs += __uint_as_float(b.y);
}
__device__ __forceinline__ void srec_sub(const unsigned* __restrict__ smA,
                                         const unsigned* __restrict__ smB,
                                         int s, unsigned* h, float& fs) {
    uint4 a = *(const uint4*)(smA + s * 4);
    uint2 b = *(const uint2*)(smB + s * 2);
    h[0] -= PLO(a.x); h[1] -= PHI(a.x);
    h[2] -= PLO(a.y); h[3] -= PHI(a.y);
    h[4] -= PLO(a.z); h[5] -= PHI(a.z);
    h[6] -= PLO(a.w); h[7] -= PHI(a.w);
    h[8] -= PLO(b.x); h[9] -= PHI(b.x);
    fs -= __uint_as_float(b.y);
}

__global__ __launch_bounds__(W_IN, 3) void fusedBC(float* __restrict__ out) {
    extern __shared__ unsigned sm[];
    unsigned* smA = sm;                          // HB * STRIDE_A words
    unsigned* smB = sm + HB * STRIDE_A;          // HB * STRIDE_B words
    const int x0 = blockIdx.x * W_OUT;
    const int y0 = blockIdx.y * HB;
    const int tid = threadIdx.x;

    // ------------- Phase 1: vertical 33-tap sliders, 1 column/thread --------
    {
        const int j = tid;                       // 0..287
        int xg = x0 - RAD + j;
        bool valid = (xg >= 0) && (xg < WW);

        unsigned long long w0 = 0, w1 = 0;
        unsigned w2 = 0;
        float fs = 0.f;
        if (valid) {
#pragma unroll
            for (int yi = 0; yi < 33; yi++) {
                int y = y0 - RAD + yi;
                if (y >= 0 && y < HH) {
                    unsigned u = g_packed[y * WW + xg];
                    fs += __half2float(__ushort_as_half((unsigned short)u));
                    pk_add(w0, w1, w2, (int)(u >> 16));
                }
            }
        }
#pragma unroll
        for (int r = 0; r < HB; r++) {
            *(uint4*)(smA + r * STRIDE_A + j * 4) =
                make_uint4((unsigned)w0, (unsigned)(w0 >> 32),
                           (unsigned)w1, (unsigned)(w1 >> 32));
            *(uint2*)(smB + r * STRIDE_B + j * 2) =
                make_uint2(w2, __float_as_uint(fs));
            if (valid) {
                int ya = y0 + r + RAD + 1;
                if (ya < HH) {
                    unsigned u = g_packed[ya * WW + xg];
                    fs += __half2float(__ushort_as_half((unsigned short)u));
                    pk_add(w0, w1, w2, (int)(u >> 16));
                }
                int yr = y0 + r - RAD;
                if (yr >= 0) {
                    unsigned u = g_packed[yr * WW + xg];
                    fs -= __half2float(__ushort_as_half((unsigned short)u));
                    pk_sub(w0, w1, w2, (int)(u >> 16));
                }
            }
        }
    }
    __syncthreads();

    // ------------- Phase 2: horizontal 33-tap sliders (256 tasks) -----------
    if (tid < 256) {
        const int r = tid & 7;      // low bits -> conflict-free LDS phases
        const int c = tid >> 3;
        const int xo = x0 + c * CHC_F;
        const unsigned* rowA = smA + r * STRIDE_A;
        const unsigned* rowB = smB + r * STRIDE_B;

        int yy = y0 + r;
        int wy = min(yy + RAD, HH - 1) - max(yy - RAD, 0) + 1;

        unsigned h[10];
#pragma unroll
        for (int i = 0; i < 10; i++) h[i] = 0;
        float fs = 0.f;

#pragma unroll
        for (int si = 0; si < 33; si++)
            srec_add(rowA, rowB, c * CHC_F + si, h, fs);

#pragma unroll
        for (int k4 = 0; k4 < CHC_F / 4; k4++) {
            float s4[4], i4[4], u4[4];
#pragma unroll
            for (int kk = 0; kk < 4; kk++) {
                int k = k4 * 4 + kk;
                int x = xo + k;
                int wx = min(x + RAD, WW - 1) - max(x - RAD, 0) + 1;
                float fcount = (float)(wx * wy);   // exact window size
                float invc = __frcp_rn(fcount);
                float eps = 1e-6f * fcount;

                float acc0 = 0.f, acc1 = 0.f;      // two chains for ILP
#pragma unroll
                for (int p = 0; p < 10; p++) {
                    float slo = (float)(h[p] & 0xFFFFu);
                    float shi = (float)(h[p] >> 16);
                    acc0 += slo * __logf(slo + eps);   // 0*log(eps) == 0
                    if (p != 9)                         // lane 19 is zero pad
                        acc1 += shi * __logf(shi + eps);
                }
                float impurity = (__logf(fcount) - (acc0 + acc1) * invc)
                                 * INV_LOG19;
                float unc = fs * invc;

                s4[kk] = impurity * unc;
                i4[kk] = impurity;
                u4[kk] = unc;

                if (k < CHC_F - 1) {
                    srec_add(rowA, rowB, c * CHC_F + k + 33, h, fs);
                    srec_sub(rowA, rowB, c * CHC_F + k, h, fs);
                }
            }
            int o = yy * WW + xo + k4 * 4;
            *(float4*)(out + o)            = make_float4(s4[0], s4[1], s4[2], s4[3]);
            *(float4*)(out + HWSZ + o)     = make_float4(i4[0], i4[1], i4[2], i4[3]);
            *(float4*)(out + 2 * HWSZ + o) = make_float4(u4[0], u4[1], u4[2], u4[3]);
        }
    }
}

// ============================================================================
extern "C" void kernel_launch(void* const* d_in, const int* in_sizes, int n_in,
                              void* d_out, int out_size) {
    const float* logit = (const float*)d_in[0];
    const float* cw    = (const float*)d_in[1];
    float* out = (float*)d_out;

    cudaFuncSetAttribute(fusedBC, cudaFuncAttributeMaxDynamicSharedMemorySize,
                         SMEM_BYTES);

    passA<<<HWSZ / 256, 256>>>(logit, cw);
    fusedBC<<<dim3(WW / W_OUT, HH / HB), W_IN, SMEM_BYTES>>>(out);
}